// round 1
// baseline (speedup 1.0000x reference)
#include <cuda_runtime.h>

// Global fp64 accumulators: [0]=cwg sum, [1]=dcml sum, [2]=tv sum (y+x combined)
__device__ double g_acc[3];

__global__ void k_init() {
    if (threadIdx.x < 3) g_acc[threadIdx.x] = 0.0;
}

__device__ __forceinline__ float fsqrt_a(float x) {
    float r; asm("sqrt.approx.f32 %0, %1;" : "=f"(r) : "f"(x)); return r;
}
__device__ __forceinline__ float fex2_a(float x) {
    float r; asm("ex2.approx.f32 %0, %1;" : "=f"(r) : "f"(x)); return r;
}

// ---------------------------------------------------------------------------
// CWG: one block per (b,p). Skips masked rows entirely (sim is multiplied by
// mask[b,p] in the reference, and the mean denominator is a constant).
// prob = exp(-sqrt(dy^2+dx^2)/2) = 2^(-0.72134752 * d)  -> 1 SQRT + 1 EX2 MUFU.
// ---------------------------------------------------------------------------
__global__ __launch_bounds__(256) void k_cwg(const float* __restrict__ sim,
                                             const float* __restrict__ wc,
                                             const unsigned* __restrict__ mask)
{
    const int bp = blockIdx.x;           // b*4096 + p
    if (mask[bp] == 0u) return;          // works for int32 {0,1} or fp32 {0.,1.} encodings

    const float yc = wc[2 * bp + 0];
    const float xc = wc[2 * bp + 1];
    const float4* __restrict__ s4 = reinterpret_cast<const float4*>(sim) + (size_t)bp * 1024;

    const int t = threadIdx.x;
    const float C = -0.721347520444482f;   // -1/(2*ln2)
    float acc = 0.0f;

#pragma unroll
    for (int it = 0; it < 4; ++it) {
        const int v = t + it * 256;        // float4 index within the 64x64 tile
        const float4 s = s4[v];
        const int e = v << 2;              // element index; 4 | 64 so i is constant per float4
        const float di  = (float)(e >> 6) - yc;
        const float dj  = (float)(e & 63) - xc;
        const float dy2 = di * di;
        const float r0 = fmaf(dj,        dj,        dy2);
        const float r1 = fmaf(dj + 1.f,  dj + 1.f,  dy2);
        const float r2 = fmaf(dj + 2.f,  dj + 2.f,  dy2);
        const float r3 = fmaf(dj + 3.f,  dj + 3.f,  dy2);
        acc = fmaf(s.x, fex2_a(C * fsqrt_a(r0)), acc);
        acc = fmaf(s.y, fex2_a(C * fsqrt_a(r1)), acc);
        acc = fmaf(s.z, fex2_a(C * fsqrt_a(r2)), acc);
        acc = fmaf(s.w, fex2_a(C * fsqrt_a(r3)), acc);
    }

    // block reduction (8 warps)
#pragma unroll
    for (int o = 16; o; o >>= 1) acc += __shfl_xor_sync(0xFFFFFFFFu, acc, o);
    __shared__ float ws[8];
    if ((t & 31) == 0) ws[t >> 5] = acc;
    __syncthreads();
    if (t < 8) {
        float v = ws[t];
#pragma unroll
        for (int o = 4; o; o >>= 1) v += __shfl_xor_sync(0xFFu, v, o);
        if (t == 0) atomicAdd(&g_acc[0], (double)v);
    }
}

// ---------------------------------------------------------------------------
// Small losses. Blocks 0..255: DCML lines (per batch: 64 rows using x, then 64
// cols using y). Block 256: TV.  64 threads per block.
// ---------------------------------------------------------------------------
__global__ __launch_bounds__(64) void k_small(const float* __restrict__ wc,
                                              const unsigned* __restrict__ mask)
{
    const int t = threadIdx.x;

    if (blockIdx.x < 256) {
        // ---- DCML: one line (row or column) per block ----
        const int L = blockIdx.x;
        const int b = L >> 7;          // 0..1
        const int r = L & 127;         // 0..127: rows 0..63 (x), cols 64..127 (y)
        int p, comp;
        if (r < 64) { p = r * 64 + t;        comp = 1; }   // row r, element j=t, use x
        else        { p = t * 64 + (r - 64); comp = 0; }   // col r-64, element i=t, use y

        const int bp = b * 4096 + p;
        __shared__ float sv[64];
        __shared__ float sm[64];
        sv[t] = wc[2 * bp + comp];
        sm[t] = (mask[bp] != 0u) ? 1.0f : 0.0f;
        __syncthreads();

        float acc = 0.0f;
        if (sm[t] != 0.0f) {
            const float vt = sv[t];
            for (int q = t + 1; q < 64; ++q)
                acc += fmaxf(sv[q] - vt, 0.0f) * sm[q];
        }
#pragma unroll
        for (int o = 16; o; o >>= 1) acc += __shfl_xor_sync(0xFFFFFFFFu, acc, o);
        __shared__ float ws2[2];
        if ((t & 31) == 0) ws2[t >> 5] = acc;
        __syncthreads();
        if (t == 0) atomicAdd(&g_acc[1], (double)(ws2[0] + ws2[1]));
    } else {
        // ---- TV: y-pairs [2][63][64] and x-pairs [2][64][63], 2 comps each ----
        float acc = 0.0f;
        // y direction
        for (int idx = t; idx < 2 * 63 * 64; idx += 64) {
            const int b = idx / (63 * 64);
            const int rem = idx - b * 63 * 64;
            const int i = rem >> 6, j = rem & 63;
            const int p0 = b * 4096 + i * 64 + j;
            const int p1 = p0 + 64;
            if (mask[p0] != 0u && mask[p1] != 0u) {
                const float d0 = wc[2 * p1 + 0] - wc[2 * p0 + 0];
                const float d1 = wc[2 * p1 + 1] - wc[2 * p0 + 1];
                acc = fmaf(d0, d0, acc);
                acc = fmaf(d1, d1, acc);
            }
        }
        // x direction
        for (int idx = t; idx < 2 * 64 * 63; idx += 64) {
            const int b = idx / (64 * 63);
            const int rem = idx - b * 64 * 63;
            const int i = rem / 63, j = rem - i * 63;
            const int p0 = b * 4096 + i * 64 + j;
            const int p1 = p0 + 1;
            if (mask[p0] != 0u && mask[p1] != 0u) {
                const float d0 = wc[2 * p1 + 0] - wc[2 * p0 + 0];
                const float d1 = wc[2 * p1 + 1] - wc[2 * p0 + 1];
                acc = fmaf(d0, d0, acc);
                acc = fmaf(d1, d1, acc);
            }
        }
#pragma unroll
        for (int o = 16; o; o >>= 1) acc += __shfl_xor_sync(0xFFFFFFFFu, acc, o);
        __shared__ float ws3[2];
        if ((t & 31) == 0) ws3[t >> 5] = acc;
        __syncthreads();
        if (t == 0) atomicAdd(&g_acc[2], (double)(ws3[0] + ws3[1]));
    }
}

__global__ void k_fin(float* __restrict__ out)
{
    // cwg  = -2.0  * mean over 2*4096*64*64 = 33554432 elements
    // tv   =  1e-4 * (Sy/16128 + Sx/16128)  (Sy+Sx accumulated together)
    // dcml = -0.01 * mean over 2*4096*4096  = 33554432 elements
    const double cwg  = -2.0  * g_acc[0] / 33554432.0;
    const double tv   =  1e-4 * g_acc[2] / 16128.0;
    const double dcml = -0.01 * g_acc[1] / 33554432.0;
    out[0] = (float)(cwg + tv + dcml);
}

extern "C" void kernel_launch(void* const* d_in, const int* in_sizes, int n_in,
                              void* d_out, int out_size)
{
    const float*    sim  = nullptr;
    const float*    wc   = nullptr;
    const unsigned* mask = nullptr;
    for (int i = 0; i < n_in; ++i) {
        if      (in_sizes[i] == 33554432) sim  = (const float*)d_in[i];
        else if (in_sizes[i] == 16384)    wc   = (const float*)d_in[i];
        else if (in_sizes[i] == 8192)     mask = (const unsigned*)d_in[i];
    }

    k_init<<<1, 32>>>();
    k_cwg<<<8192, 256>>>(sim, wc, mask);
    k_small<<<257, 64>>>(wc, mask);
    k_fin<<<1, 1>>>((float*)d_out);
}

// round 2
// speedup vs baseline: 2.4480x; 2.4480x over previous
#include <cuda_runtime.h>

// fp64 accumulators: [0]=cwg sum, [1]=dcml sum, [2]=tv sum. Zero at load,
// re-zeroed by the last block each call -> deterministic & graph-safe.
__device__ double   g_acc[3];
__device__ unsigned g_done = 0;

#define N_CWG_BLOCKS  1024   // 8 (b,p) rows each
#define N_DCML_BLOCKS 64     // 4 lines each (256 lines total)
#define N_TV_BLOCKS   1
#define N_TOTAL (N_CWG_BLOCKS + N_DCML_BLOCKS + N_TV_BLOCKS)

__device__ __forceinline__ float fsqrt_a(float x) {
    float r; asm("sqrt.approx.f32 %0, %1;" : "=f"(r) : "f"(x)); return r;
}
__device__ __forceinline__ float fex2_a(float x) {
    float r; asm("ex2.approx.f32 %0, %1;" : "=f"(r) : "f"(x)); return r;
}

// 256-thread block reduction to a single float (returned on thread 0)
__device__ __forceinline__ float block_reduce_256(float v) {
    __shared__ float ws[8];
    const int t = threadIdx.x;
#pragma unroll
    for (int o = 16; o; o >>= 1) v += __shfl_xor_sync(0xFFFFFFFFu, v, o);
    if ((t & 31) == 0) ws[t >> 5] = v;
    __syncthreads();
    float r = 0.0f;
    if (t < 8) {
        r = ws[t];
#pragma unroll
        for (int o = 4; o; o >>= 1) r += __shfl_xor_sync(0xFFu, r, o);
    }
    return r;
}

__global__ __launch_bounds__(256) void k_fused(const float* __restrict__ sim,
                                               const float* __restrict__ wc,
                                               const unsigned* __restrict__ mask,
                                               float* __restrict__ out)
{
    const int t   = threadIdx.x;
    const int blk = blockIdx.x;

    if (blk < N_CWG_BLOCKS) {
        // ------------------ CWG: 8 rows (b,p) per block ------------------
        const float C = -0.721347520444482f;   // -1/(2*ln2): exp(-d/2)=2^(C*d)
        float acc = 0.0f;
#pragma unroll 1
        for (int k = 0; k < 8; ++k) {
            const int bp = blk * 8 + k;
            if (mask[bp] == 0u) continue;      // sim row is zeroed by mask in ref
            const float yc = wc[2 * bp + 0];
            const float xc = wc[2 * bp + 1];
            const float4* __restrict__ s4 =
                reinterpret_cast<const float4*>(sim) + (size_t)bp * 1024;
#pragma unroll
            for (int it = 0; it < 4; ++it) {
                const int v = t + it * 256;      // float4 idx in 64x64 tile
                const float4 s = s4[v];
                const int e = v << 2;            // 4 | 64 -> row const per float4
                const float di  = (float)(e >> 6) - yc;
                const float dj  = (float)(e & 63) - xc;
                const float dy2 = di * di;
                const float r0 = fmaf(dj,       dj,       dy2);
                const float r1 = fmaf(dj + 1.f, dj + 1.f, dy2);
                const float r2 = fmaf(dj + 2.f, dj + 2.f, dy2);
                const float r3 = fmaf(dj + 3.f, dj + 3.f, dy2);
                acc = fmaf(s.x, fex2_a(C * fsqrt_a(r0)), acc);
                acc = fmaf(s.y, fex2_a(C * fsqrt_a(r1)), acc);
                acc = fmaf(s.z, fex2_a(C * fsqrt_a(r2)), acc);
                acc = fmaf(s.w, fex2_a(C * fsqrt_a(r3)), acc);
            }
        }
        const float bs = block_reduce_256(acc);
        if (t == 0 && bs != 0.0f) atomicAdd(&g_acc[0], (double)bs);
    }
    else if (blk < N_CWG_BLOCKS + N_DCML_BLOCKS) {
        // ------------------ DCML: 4 lines per block ------------------
        // Line L (0..255): b=L>>7; r=L&127. r<64: row r (x comp), else col (y).
        const int g = t >> 6;           // group 0..3
        const int u = t & 63;           // element within line
        const int L = (blk - N_CWG_BLOCKS) * 4 + g;
        const int b = L >> 7;
        const int r = L & 127;
        int p, comp;
        if (r < 64) { p = r * 64 + u;        comp = 1; }
        else        { p = u * 64 + (r - 64); comp = 0; }
        const int bp = b * 4096 + p;

        __shared__ float sv[4][64];
        __shared__ float sm[4][64];
        sv[g][u] = wc[2 * bp + comp];
        sm[g][u] = (mask[bp] != 0u) ? 1.0f : 0.0f;
        __syncthreads();

        float acc = 0.0f;
        if (sm[g][u] != 0.0f) {
            const float vt = sv[g][u];
            for (int q = u + 1; q < 64; ++q)
                acc += fmaxf(sv[g][q] - vt, 0.0f) * sm[g][q];
        }
        const float bs = block_reduce_256(acc);
        if (t == 0) atomicAdd(&g_acc[1], (double)bs);
    }
    else {
        // ------------------ TV: one block, 256 threads ------------------
        float acc = 0.0f;
        for (int idx = t; idx < 2 * 63 * 64; idx += 256) {   // y-direction pairs
            const int b = idx / (63 * 64);
            const int rem = idx - b * 63 * 64;
            const int i = rem >> 6, j = rem & 63;
            const int p0 = b * 4096 + i * 64 + j;
            const int p1 = p0 + 64;
            if (mask[p0] != 0u && mask[p1] != 0u) {
                const float d0 = wc[2 * p1 + 0] - wc[2 * p0 + 0];
                const float d1 = wc[2 * p1 + 1] - wc[2 * p0 + 1];
                acc = fmaf(d0, d0, acc);
                acc = fmaf(d1, d1, acc);
            }
        }
        for (int idx = t; idx < 2 * 64 * 63; idx += 256) {   // x-direction pairs
            const int b = idx / (64 * 63);
            const int rem = idx - b * 64 * 63;
            const int i = rem / 63, j = rem - i * 63;
            const int p0 = b * 4096 + i * 64 + j;
            const int p1 = p0 + 1;
            if (mask[p0] != 0u && mask[p1] != 0u) {
                const float d0 = wc[2 * p1 + 0] - wc[2 * p0 + 0];
                const float d1 = wc[2 * p1 + 1] - wc[2 * p0 + 1];
                acc = fmaf(d0, d0, acc);
                acc = fmaf(d1, d1, acc);
            }
        }
        const float bs = block_reduce_256(acc);
        if (t == 0) atomicAdd(&g_acc[2], (double)bs);
    }

    // ---------------- completion: last block finalizes ----------------
    __threadfence();
    __syncthreads();
    if (t == 0) {
        const unsigned prev = atomicAdd(&g_done, 1u);
        if (prev == N_TOTAL - 1) {
            __threadfence();
            const double s0 = g_acc[0], s1 = g_acc[1], s2 = g_acc[2];
            const double cwg  = -2.0  * s0 / 33554432.0;  // mean over 2*4096*64*64
            const double dcml = -0.01 * s1 / 33554432.0;  // mean over 2*4096*4096
            const double tv   =  1e-4 * s2 / 16128.0;     // Sy/16128 + Sx/16128
            out[0] = (float)(cwg + tv + dcml);
            g_acc[0] = 0.0; g_acc[1] = 0.0; g_acc[2] = 0.0;
            g_done = 0u;
        }
    }
}

extern "C" void kernel_launch(void* const* d_in, const int* in_sizes, int n_in,
                              void* d_out, int out_size)
{
    const float*    sim  = nullptr;
    const float*    wc   = nullptr;
    const unsigned* mask = nullptr;
    for (int i = 0; i < n_in; ++i) {
        if      (in_sizes[i] == 33554432) sim  = (const float*)d_in[i];
        else if (in_sizes[i] == 16384)    wc   = (const float*)d_in[i];
        else if (in_sizes[i] == 8192)     mask = (const unsigned*)d_in[i];
    }
    k_fused<<<N_TOTAL, 256>>>(sim, wc, mask, (float*)d_out);
}

// round 5
// speedup vs baseline: 2.6010x; 1.0625x over previous
#include <cuda_runtime.h>

// fp64 accumulators: [0]=cwg, [1]=dcml, [2]=tv. Reset by last block each call.
__device__ double   g_acc[3];
__device__ unsigned g_done   = 0;
__device__ unsigned g_ticket = 0;

#define N_CWG_BLOCKS  1119
#define N_DCML_BLOCKS 64     // 4 lines each (256 lines total)
#define N_TV_BLOCKS   1
#define N_TOTAL (N_CWG_BLOCKS + N_DCML_BLOCKS + N_TV_BLOCKS)   // 1184 = 148*8
#define ROWS_TOTAL 8192
#define GRAIN 2

__device__ __forceinline__ float fsqrt_a(float x) {
    float r; asm("sqrt.approx.f32 %0, %1;" : "=f"(r) : "f"(x)); return r;
}
__device__ __forceinline__ float fex2_a(float x) {
    float r; asm("ex2.approx.f32 %0, %1;" : "=f"(r) : "f"(x)); return r;
}

__device__ __forceinline__ float block_reduce_256(float v) {
    __shared__ float ws[8];
    const int t = threadIdx.x;
#pragma unroll
    for (int o = 16; o; o >>= 1) v += __shfl_xor_sync(0xFFFFFFFFu, v, o);
    if ((t & 31) == 0) ws[t >> 5] = v;
    __syncthreads();
    float r = 0.0f;
    if (t < 8) {
        r = ws[t];
#pragma unroll
        for (int o = 4; o; o >>= 1) r += __shfl_xor_sync(0xFFu, r, o);
    }
    return r;
}

__global__ __launch_bounds__(256) void k_fused(const float* __restrict__ sim,
                                               const float* __restrict__ wc,
                                               const unsigned* __restrict__ mask,
                                               float* __restrict__ out)
{
    const int t   = threadIdx.x;
    const int blk = blockIdx.x;

    if (blk < N_CWG_BLOCKS) {
        // ----- CWG: dynamic row stealing (grain=2) with prefetched ticket -----
        const float C = -0.721347520444482f;   // -1/(2*ln2): exp(-d/2)=2^(C*d)
        float acc = 0.0f;
        __shared__ int s_base;
        int next = 0;
        if (t == 0) {
            next = (int)atomicAdd(&g_ticket, GRAIN);
            s_base = next;
        }
        __syncthreads();
        for (;;) {
            const int base = s_base;
            if (base >= ROWS_TOTAL) break;
            // prefetch next ticket NOW; publish after the work (hides RED latency)
            if (t == 0) next = (int)atomicAdd(&g_ticket, GRAIN);
#pragma unroll 1
            for (int k = 0; k < GRAIN; ++k) {
                const int bp = base + k;
                if (mask[bp] == 0u) continue;       // masked row: sim zeroed in ref
                const float yc = wc[2 * bp + 0];
                const float xc = wc[2 * bp + 1];
                const float4* __restrict__ s4 =
                    reinterpret_cast<const float4*>(sim) + (size_t)bp * 1024;
#pragma unroll
                for (int it = 0; it < 4; ++it) {
                    const int v = t + it * 256;      // float4 idx in 64x64 tile
                    const float4 s = s4[v];
                    const int e = v << 2;            // 4 | 64 -> row const
                    const float di  = (float)(e >> 6) - yc;
                    const float dj  = (float)(e & 63) - xc;
                    const float dy2 = di * di;
                    const float r0 = fmaf(dj,       dj,       dy2);
                    const float r1 = fmaf(dj + 1.f, dj + 1.f, dy2);
                    const float r2 = fmaf(dj + 2.f, dj + 2.f, dy2);
                    const float r3 = fmaf(dj + 3.f, dj + 3.f, dy2);
                    acc = fmaf(s.x, fex2_a(C * fsqrt_a(r0)), acc);
                    acc = fmaf(s.y, fex2_a(C * fsqrt_a(r1)), acc);
                    acc = fmaf(s.z, fex2_a(C * fsqrt_a(r2)), acc);
                    acc = fmaf(s.w, fex2_a(C * fsqrt_a(r3)), acc);
                }
            }
            __syncthreads();                 // everyone done reading s_base
            if (t == 0) s_base = next;       // publish prefetched ticket
            __syncthreads();
        }
        const float bs = block_reduce_256(acc);
        if (t == 0 && bs != 0.0f) atomicAdd(&g_acc[0], (double)bs);
    }
    else if (blk < N_CWG_BLOCKS + N_DCML_BLOCKS) {
        // ---------- DCML: 4 lines per block ----------
        const int g = t >> 6;           // group 0..3
        const int u = t & 63;           // element within line
        const int L = (blk - N_CWG_BLOCKS) * 4 + g;
        const int b = L >> 7;
        const int r = L & 127;
        int p, comp;
        if (r < 64) { p = r * 64 + u;        comp = 1; }   // row r -> x
        else        { p = u * 64 + (r - 64); comp = 0; }   // col   -> y
        const int bp = b * 4096 + p;

        __shared__ float sv[4][64];
        __shared__ float sm[4][64];
        sv[g][u] = wc[2 * bp + comp];
        sm[g][u] = (mask[bp] != 0u) ? 1.0f : 0.0f;
        __syncthreads();

        float acc = 0.0f;
        if (sm[g][u] != 0.0f) {
            const float vt = sv[g][u];
            for (int q = u + 1; q < 64; ++q)
                acc += fmaxf(sv[g][q] - vt, 0.0f) * sm[g][q];
        }
        const float bs = block_reduce_256(acc);
        if (t == 0) atomicAdd(&g_acc[1], (double)bs);
    }
    else {
        // ---------- TV: one block ----------
        float acc = 0.0f;
        for (int idx = t; idx < 2 * 63 * 64; idx += 256) {   // y-pairs
            const int b = idx / (63 * 64);
            const int rem = idx - b * 63 * 64;
            const int i = rem >> 6, j = rem & 63;
            const int p0 = b * 4096 + i * 64 + j;
            const int p1 = p0 + 64;
            if (mask[p0] != 0u && mask[p1] != 0u) {
                const float d0 = wc[2 * p1 + 0] - wc[2 * p0 + 0];
                const float d1 = wc[2 * p1 + 1] - wc[2 * p0 + 1];
                acc = fmaf(d0, d0, acc);
                acc = fmaf(d1, d1, acc);
            }
        }
        for (int idx = t; idx < 2 * 64 * 63; idx += 256) {   // x-pairs
            const int b = idx / (64 * 63);
            const int rem = idx - b * 64 * 63;
            const int i = rem / 63, j = rem - i * 63;
            const int p0 = b * 4096 + i * 64 + j;
            const int p1 = p0 + 1;
            if (mask[p0] != 0u && mask[p1] != 0u) {
                const float d0 = wc[2 * p1 + 0] - wc[2 * p0 + 0];
                const float d1 = wc[2 * p1 + 1] - wc[2 * p0 + 1];
                acc = fmaf(d0, d0, acc);
                acc = fmaf(d1, d1, acc);
            }
        }
        const float bs = block_reduce_256(acc);
        if (t == 0) atomicAdd(&g_acc[2], (double)bs);
    }

    // ---------- completion: last block finalizes & resets state ----------
    __threadfence();
    __syncthreads();
    if (t == 0) {
        const unsigned prev = atomicAdd(&g_done, 1u);
        if (prev == N_TOTAL - 1) {
            __threadfence();
            const double s0 = g_acc[0], s1 = g_acc[1], s2 = g_acc[2];
            const double cwg  = -2.0  * s0 / 33554432.0;  // mean 2*4096*64*64
            const double dcml = -0.01 * s1 / 33554432.0;  // mean 2*4096*4096
            const double tv   =  1e-4 * s2 / 16128.0;     // Sy/16128 + Sx/16128
            out[0] = (float)(cwg + tv + dcml);
            g_acc[0] = 0.0; g_acc[1] = 0.0; g_acc[2] = 0.0;
            g_ticket = 0u;
            g_done   = 0u;
        }
    }
}

extern "C" void kernel_launch(void* const* d_in, const int* in_sizes, int n_in,
                              void* d_out, int out_size)
{
    const float*    sim  = nullptr;
    const float*    wc   = nullptr;
    const unsigned* mask = nullptr;
    for (int i = 0; i < n_in; ++i) {
        if      (in_sizes[i] == 33554432) sim  = (const float*)d_in[i];
        else if (in_sizes[i] == 16384)    wc   = (const float*)d_in[i];
        else if (in_sizes[i] == 8192)     mask = (const unsigned*)d_in[i];
    }
    k_fused<<<N_TOTAL, 256>>>(sim, wc, mask, (float*)d_out);
}